// round 15
// baseline (speedup 1.0000x reference)
#include <cuda_runtime.h>
#include <cuda_fp16.h>
#include <math.h>
#include <stdint.h>

#define NB 4
#define NH 12
#define NSEQ 2048
#define HD 64
#define NROWS (NB*NH*NSEQ)   // 98304

// Scratch (allocation-free rule: __device__ globals). K layernormed, V copied,
// both fp16, row-major [B,H,N,d] planes.
__device__ __half g_k[(size_t)NROWS*HD];
__device__ __half g_v[(size_t)NROWS*HD];

// ---------------------------------------------------------------------------
__device__ __forceinline__ uint32_t smem_u32(const void* p) {
    uint32_t a;
    asm("{ .reg .u64 t; cvta.to.shared.u64 t, %1; cvt.u32.u64 %0, t; }" : "=r"(a) : "l"(p));
    return a;
}
#define CP16(s, g) asm volatile("cp.async.cg.shared.global [%0], [%1], 16;" :: "r"(s), "l"(g))
#define CP_COMMIT() asm volatile("cp.async.commit_group;" ::: "memory")
#define CP_WAIT0()  asm volatile("cp.async.wait_group 0;" ::: "memory")

__device__ __forceinline__ void ldsm_x2t(uint32_t& r0, uint32_t& r1, uint32_t a) {
    asm volatile("ldmatrix.sync.aligned.m8n8.x2.trans.shared.b16 {%0,%1}, [%2];"
                 : "=r"(r0), "=r"(r1) : "r"(a));
}
__device__ __forceinline__ void ldsm_x4(uint32_t* r, uint32_t a) {
    asm volatile("ldmatrix.sync.aligned.m8n8.x4.shared.b16 {%0,%1,%2,%3}, [%4];"
                 : "=r"(r[0]), "=r"(r[1]), "=r"(r[2]), "=r"(r[3]) : "r"(a));
}
__device__ __forceinline__ void ldsm_x4t(uint32_t* r, uint32_t a) {
    asm volatile("ldmatrix.sync.aligned.m8n8.x4.trans.shared.b16 {%0,%1,%2,%3}, [%4];"
                 : "=r"(r[0]), "=r"(r[1]), "=r"(r[2]), "=r"(r[3]) : "r"(a));
}
// D += A*B, m16n8k16 fp16 in / fp32 accum, row.col
__device__ __forceinline__ void mma_f16(float* c, const uint32_t* a, uint32_t b0, uint32_t b1) {
    asm volatile("mma.sync.aligned.m16n8k16.row.col.f32.f16.f16.f32 "
        "{%0,%1,%2,%3}, {%4,%5,%6,%7}, {%8,%9}, {%0,%1,%2,%3};"
        : "+f"(c[0]), "+f"(c[1]), "+f"(c[2]), "+f"(c[3])
        : "r"(a[0]), "r"(a[1]), "r"(a[2]), "r"(a[3]), "r"(b0), "r"(b1));
}
__device__ __forceinline__ float ex2f(float x) {
    float y;
    asm("ex2.approx.f32 %0, %1;" : "=f"(y) : "f"(x));
    return y;
}

// ---------------------------------------------------------------------------
// Kernel 1: per-head LayerNorm on K + copy V, fp16 out, [B,H,N,d] planes.
// ---------------------------------------------------------------------------
__global__ __launch_bounds__(128) void ln_kernel(
    const float* __restrict__ qkv,
    const float* __restrict__ k_scale, const float* __restrict__ k_bias)
{
    int w    = blockIdx.x * 4 + (threadIdx.x >> 5);
    int lane = threadIdx.x & 31;
    int h  = w % NH;
    int bn = w / NH;
    int b  = bn / NSEQ;
    int n  = bn % NSEQ;

    const float* src = qkv + (size_t)bn * (3*NH*HD) + h*HD;
    size_t obase = ((size_t)(b*NH + h) * NSEQ + n) * HD;

    {   // k: layernorm -> fp16
        const float2 x = *(const float2*)(src + NH*HD + 2*lane);
        float s = x.x + x.y, s2 = x.x*x.x + x.y*x.y;
        #pragma unroll
        for (int o = 16; o; o >>= 1) {
            s  += __shfl_xor_sync(0xffffffffu, s,  o);
            s2 += __shfl_xor_sync(0xffffffffu, s2, o);
        }
        float mean = s * (1.f/HD);
        float var  = s2 * (1.f/HD) - mean*mean;
        float r = rsqrtf(var + 1e-6f);
        float y0 = (x.x-mean)*r*k_scale[2*lane]   + k_bias[2*lane];
        float y1 = (x.y-mean)*r*k_scale[2*lane+1] + k_bias[2*lane+1];
        *(half2*)(g_k + obase + 2*lane) = __floats2half2_rn(y0, y1);
    }
    {   // v: copy -> fp16
        const float2 x = *(const float2*)(src + 2*NH*HD + 2*lane);
        *(half2*)(g_v + obase + 2*lane) = __floats2half2_rn(x.x, x.y);
    }
}

// ---------------------------------------------------------------------------
// Kernel 2: fp16 m16n8k16 flash attention, chunk-pipelined, small-CTA.
// CTA = 64 q-rows of one (b,h); 128 threads, 4 warps, warp owns 16 rows.
// 4 CTAs/SM -> finer barrier granularity, cross-CTA overlap of tile phases.
// No-shift softmax: Q scaled by 0.125*log2e, p = ex2(s'); 2^-c cancels in
// the p/Σp ratio. Row sums via ones-column at V col 64 (pad, written once).
// ---------------------------------------------------------------------------
#define STR 72
#define KVH (64*STR)           // 4608 halves per tile
#define BUFH (2*KVH)           // 9216 halves per stage
#define SMB  (2*BUFH*2)        // 36864 bytes

__global__ __launch_bounds__(128, 4) void attn_mma(
    const float* __restrict__ qkv,
    const float* __restrict__ q_scale, const float* __restrict__ q_bias,
    float* __restrict__ out)
{
    extern __shared__ __align__(16) __half sm[];
    uint32_t sbase = smem_u32(sm);

    int tid = threadIdx.x;
    int w = tid >> 5, lane = tid & 31;
    int g = lane >> 2, t = lane & 3;
    int l8 = lane & 7;
    int lb3 = (lane >> 3) & 1, lb4 = (lane >> 4) & 1;
    int qt = blockIdx.x, h = blockIdx.y, b = blockIdx.z;
    size_t plane = (size_t)(b*NH + h) * NSEQ * HD;
    int m0 = w * 16;

    // ---- prologue: LN(Q) -> Qs rows 0..63 (fp16, *0.125*log2e folded) ----
    if (tid < 64) {
        int n = qt*64 + tid;
        const float* src = qkv + (size_t)(b*NSEQ + n) * (3*NH*HD) + h*HD;
        float x[64];
        float s = 0.f, s2 = 0.f;
        #pragma unroll
        for (int i = 0; i < 16; i++) {
            float4 v = *(const float4*)(src + 4*i);
            x[4*i]=v.x; x[4*i+1]=v.y; x[4*i+2]=v.z; x[4*i+3]=v.w;
            s  += v.x+v.y+v.z+v.w;
            s2 += v.x*v.x+v.y*v.y+v.z*v.z+v.w*v.w;
        }
        float mean = s * (1.f/HD);
        float var  = s2 * (1.f/HD) - mean*mean;
        float r = rsqrtf(var + 1e-6f);
        const float QS = 0.125f * 1.44269504088896f;   // 1/8 * log2(e)
        half2* qrow = (half2*)(sm + tid*STR);
        #pragma unroll
        for (int ii = 0; ii < 32; ii++) {
            int i = (ii + 4*(tid & 7)) & 31;    // stagger banks
            float y0 = ((x[2*i]  -mean)*r*q_scale[2*i]   + q_bias[2*i])   * QS;
            float y1 = ((x[2*i+1]-mean)*r*q_scale[2*i+1] + q_bias[2*i+1]) * QS;
            qrow[i] = __floats2half2_rn(y0, y1);
        }
    }
    __syncthreads();

    // ---- preload Q fragments: 4 k-chunks x ldmatrix.x4 -> 16 regs ----
    uint32_t Qreg[4][4];
    {
        uint32_t qa = sbase + ((m0 + lb3*8 + l8)*STR)*2 + lb4*16;
        #pragma unroll
        for (int kc = 0; kc < 4; kc++)
            ldsm_x4(Qreg[kc], qa + kc*32);
    }
    __syncthreads();   // Qs dead; smem belongs to K/V buffers now

    // ---- ones-column init: V pad cols 64..71, both buffers (stable) ----
    if (tid < 128) {
        int r = tid & 63, bf = tid >> 6;
        uint4* p = (uint4*)(sm + (size_t)bf*BUFH + KVH + r*STR + 64);
        *p = make_uint4(0x00003C00u, 0u, 0u, 0u);   // {1.0h, 0...}
    }

    const __half* Kg = g_k + plane;
    const __half* Vg = g_v + plane;

    // issue tile 0 into buf0
    {
        #pragma unroll
        for (int i = 0; i < 4; i++) {
            int c = tid + i*128;
            int r = c >> 3, sgm = c & 7;
            uint32_t so = (uint32_t)(r*STR + sgm*8) * 2;
            CP16(sbase + so,         Kg + r*HD + sgm*8);
            CP16(sbase + KVH*2 + so, Vg + r*HD + sgm*8);
        }
        CP_COMMIT();
    }

    float oc[9][4];
    #pragma unroll
    for (int n = 0; n < 9; n++)
        #pragma unroll
        for (int e = 0; e < 4; e++) oc[n][e] = 0.f;

    // per-thread ldmatrix lane offsets
    uint32_t kfoff  = (uint32_t)((l8 + 8*lb4)*STR + 8*lb3) * 2;
    uint32_t vfoff  = (uint32_t)((8*lb3 + l8)*STR) * 2 + lb4*16;
    uint32_t vfoff2 = (uint32_t)((8*lb3 + l8)*STR) * 2;

    for (int kt = 0; kt < NSEQ/64; kt++) {
        uint32_t buf = sbase + (uint32_t)(kt & 1) * (BUFH*2);
        CP_WAIT0();
        __syncthreads();

        if (kt + 1 < NSEQ/64) {   // prefetch next tile into other buffer
            const __half* Kt = Kg + (size_t)(kt+1)*64*HD;
            const __half* Vt = Vg + (size_t)(kt+1)*64*HD;
            uint32_t nb = sbase + (uint32_t)((kt+1) & 1) * (BUFH*2);
            #pragma unroll
            for (int i = 0; i < 4; i++) {
                int c = tid + i*128;
                int r = c >> 3, sgm = c & 7;
                uint32_t so = (uint32_t)(r*STR + sgm*8) * 2;
                CP16(nb + so,         Kt + r*HD + sgm*8);
                CP16(nb + KVH*2 + so, Vt + r*HD + sgm*8);
            }
            CP_COMMIT();
        }

        uint32_t vbuf = buf + KVH*2;

        // ---- 4 independent 16-key chunks: QK(p) -> softmax(p) -> PV(p) ----
        #pragma unroll
        for (int p = 0; p < 4; p++) {
            // S' for keys 16p..16p+15
            float sc0[4] = {0.f,0.f,0.f,0.f};
            float sc1[4] = {0.f,0.f,0.f,0.f};
            uint32_t ka = buf + kfoff + (uint32_t)(16*p*STR)*2;
            #pragma unroll
            for (int kc = 0; kc < 4; kc++) {
                uint32_t r[4];
                ldsm_x4(r, ka + kc*32);
                mma_f16(sc0, Qreg[kc], r[0], r[1]);
                mma_f16(sc1, Qreg[kc], r[2], r[3]);
            }

            // softmax: p = ex2(s'), pack straight to the A-frag for chunk p
            uint32_t Af[4];
            {
                half2 h01 = __floats2half2_rn(ex2f(sc0[0]), ex2f(sc0[1]));
                half2 h23 = __floats2half2_rn(ex2f(sc0[2]), ex2f(sc0[3]));
                Af[0] = *(uint32_t*)&h01;
                Af[1] = *(uint32_t*)&h23;
                half2 g01 = __floats2half2_rn(ex2f(sc1[0]), ex2f(sc1[1]));
                half2 g23 = __floats2half2_rn(ex2f(sc1[2]), ex2f(sc1[3]));
                Af[2] = *(uint32_t*)&g01;
                Af[3] = *(uint32_t*)&g23;
            }

            // O += P(chunk p) * V(rows 16p..16p+15)  (+ ones column -> oc[8])
            uint32_t va = vbuf + (uint32_t)(16*p*STR)*2;
            #pragma unroll
            for (int nn = 0; nn < 8; nn += 2) {
                uint32_t r[4];
                ldsm_x4t(r, va + vfoff + nn*16);
                mma_f16(oc[nn],   Af, r[0], r[1]);
                mma_f16(oc[nn+1], Af, r[2], r[3]);
            }
            uint32_t b0, b1;
            ldsm_x2t(b0, b1, va + vfoff2 + 128);   // col 64 (ones)
            mma_f16(oc[8], Af, b0, b1);
        }
    }

    // ---- epilogue: O / l -> out[b][h][q][d] ----
    {
        float l0 = __shfl_sync(0xffffffffu, oc[8][0], lane & 28);
        float l1 = __shfl_sync(0xffffffffu, oc[8][2], lane & 28);
        float rl0 = 1.f / l0;
        float rl1 = 1.f / l1;
        float* d0 = out + plane + (size_t)(qt*64 + m0 + g) * HD;
        float* d1 = d0 + 8*HD;
        #pragma unroll
        for (int nn = 0; nn < 8; nn++) {
            *(float2*)&d0[8*nn + 2*t] = make_float2(oc[nn][0]*rl0, oc[nn][1]*rl0);
            *(float2*)&d1[8*nn + 2*t] = make_float2(oc[nn][2]*rl1, oc[nn][3]*rl1);
        }
    }
}

// ---------------------------------------------------------------------------
extern "C" void kernel_launch(void* const* d_in, const int* in_sizes, int n_in,
                              void* d_out, int out_size)
{
    const float* qkv = (const float*)d_in[0];
    const float* qs  = (const float*)d_in[1];
    const float* qb  = (const float*)d_in[2];
    const float* ks  = (const float*)d_in[3];
    const float* kb  = (const float*)d_in[4];
    float* out = (float*)d_out;

    ln_kernel<<<NROWS/4, 128>>>(qkv, ks, kb);

    cudaFuncSetAttribute(attn_mma,
                         cudaFuncAttributeMaxDynamicSharedMemorySize, SMB);
    dim3 grid(NSEQ/64, NH, NB);
    attn_mma<<<grid, 128, SMB>>>(qkv, qs, qb, out);
}